// round 17
// baseline (speedup 1.0000x reference)
#include <cuda_runtime.h>

// Problem constants (fixed by the dataset)
#define NB    128          // graphs (B)
#define NN    256          // nodes per graph
#define DPE   16           // D_pe / eigen dim
#define MM    4            // M psi copies
#define HPSI  32
#define HP    16
#define HG    64
#define NSUM  (NB*NN)      // 32768
#define EDGES (NSUM*16)    // 524288
#define EPG   (EDGES/NB)   // 4096 edges per graph (graph-contiguous)
#define VPAD  20           // padded row stride (floats)

typedef unsigned long long u64;

// ---------------- packed f32x2 helpers ----------------
__device__ __forceinline__ u64 pk2(float lo, float hi) {
    u64 r; asm("mov.b64 %0,{%1,%2};" : "=l"(r) : "f"(lo), "f"(hi)); return r;
}
__device__ __forceinline__ void upk2(u64 v, float& lo, float& hi) {
    asm("mov.b64 {%0,%1},%2;" : "=f"(lo), "=f"(hi) : "l"(v));
}
__device__ __forceinline__ u64 fma2(u64 a, u64 b, u64 c) {
    u64 d; asm("fma.rn.f32x2 %0,%1,%2,%3;" : "=l"(d) : "l"(a), "l"(b), "l"(c)); return d;
}
__device__ __forceinline__ u64 mul2(u64 a, u64 b) {
    u64 d; asm("mul.rn.f32x2 %0,%1,%2;" : "=l"(d) : "l"(a), "l"(b)); return d;
}
__device__ __forceinline__ u64 add2(u64 a, u64 b) {
    u64 d; asm("add.rn.f32x2 %0,%1,%2;" : "=l"(d) : "l"(a), "l"(b)); return d;
}

// warp-inclusive scan (recomputable, no cross-group registers)
__device__ __forceinline__ int warp_incl_scan(int v, int lane) {
    int incl = v;
    #pragma unroll
    for (int off = 1; off < 32; off <<= 1) {
        int x = __shfl_up_sync(0xffffffffu, incl, off);
        if (lane >= off) incl += x;
    }
    return incl;
}

// ---------------------------------------------------------------------------
// ONE fused kernel per graph. CSR build is PIGGYBACKED on the o-loop's group
// barriers (histogram g0-7, scan g8-9, scatter g10-17) to hide its latency in
// the o-loop's idle issue slots. V tile replicated to 512 rows (no wrap).
// ---------------------------------------------------------------------------
#define COMPUTE_R2(kk) do {                                                     \
    const ulonglong2* vr_ = (const ulonglong2*)&Vs[(kk)*VPAD];                  \
    ulonglong2 a_ = vr_[0], b_ = vr_[1], c_ = vr_[2], d_ = vr_[3];              \
    u64 vk_[8] = {a_.x, a_.y, b_.x, b_.y, c_.x, c_.y, d_.x, d_.y};              \
    u64 wm_[4];                                                                 \
    _Pragma("unroll")                                                           \
    for (int m_ = 0; m_ < 4; m_++) {                                            \
        u64 s_ = mul2(An2[m_][0], vk_[0]);                                      \
        _Pragma("unroll")                                                       \
        for (int j_ = 1; j_ < 8; j_++) s_ = fma2(An2[m_][j_], vk_[j_], s_);     \
        float lo_, hi_; upk2(s_, lo_, hi_);                                     \
        float w_ = lo_ + hi_;                                                   \
        wm_[m_] = pk2(w_, w_);                                                  \
    }                                                                           \
    _Pragma("unroll")                                                           \
    for (int hp_ = 0; hp_ < 8; hp_++) {                                         \
        u64 p_ = fma2(wm_[0], wp2[0][hp_], bps2[hp_]);                          \
        p_ = fma2(wm_[1], wp2[1][hp_], p_);                                     \
        p_ = fma2(wm_[2], wp2[2][hp_], p_);                                     \
        p_ = fma2(wm_[3], wp2[3][hp_], p_);                                     \
        float lo_, hi_; upk2(p_, lo_, hi_);                                     \
        lo_ = fmaxf(lo_, 0.f); hi_ = fmaxf(hi_, 0.f);                           \
        rp[hp_] = pk2(lo_, hi_);                                                \
    }                                                                           \
} while (0)

__global__ void __launch_bounds__(256) kernelF(
        const float* __restrict__ V,
        const float* __restrict__ Lambda,
        const float* __restrict__ pW1, const float* __restrict__ pb1,
        const float* __restrict__ pW2, const float* __restrict__ pb2,
        const float* __restrict__ Wp1, const float* __restrict__ bp1,
        const float* __restrict__ Wg1, const float* __restrict__ bg1,
        const float* __restrict__ Wg2, const float* __restrict__ bg2,
        const float* __restrict__ eps,
        const int*   __restrict__ batch,
        const int*   __restrict__ edge_index,
        float* __restrict__ out)
{
    extern __shared__ float sm[];
    // Persistent regions
    float* Vs      = sm;                          // 2*NN*VPAD (replicated)
    float* xch     = sm + 2*NN*VPAD;              // 8 buffers x 5120
    float* zs      = sm + 10*NN*VPAD;             // 64
    int*   srt_s   = (int*)(sm + 10*NN*VPAD + 64);              // 4096
    int*   start_s = (int*)(sm + 10*NN*VPAD + 64 + 4096);       // 257 (+3 pad)
    int*   cnt     = (int*)(sm + 10*NN*VPAD + 64 + 4096 + 260); // 256
    int*   cur     = cnt + NN;                                   // 256
    __shared__ int bnds[2];
    __shared__ int wsum[8];

    // Phase-limited aliases (epilogue) inside xch:
    float* xT   = xch;              // 5120 (x tile)
    float* Wg1s = xch + NN*VPAD;    // 1024
    float* Wg2s = Wg1s + HP*HG;     // 1024
    float* bg1s = Wg2s + HG*DPE;    // 64
    float* bg2s = bg1s + HG;        // 16

    int b = blockIdx.x;
    int n = threadIdx.x;
    int lane = n & 31;

    const int* srcp = edge_index + (size_t)b*EPG;
    const int* dstp = edge_index + (size_t)EDGES + (size_t)b*EPG;
    int base = b*NN;

    // ---- Stage V tile [256 x 16] into padded smem, REPLICATED ----
    const float4* vg = (const float4*)(V + (size_t)b*NN*DPE);
    for (int i = n; i < NN*DPE/4; i += 256) {
        float4 v = vg[i];
        int row = i >> 2, col = (i & 3) << 2;
        *(float4*)&Vs[row*VPAD + col] = v;
        *(float4*)&Vs[(row + NN)*VPAD + col] = v;
    }
    cnt[n] = 0;

    // ---- psi MLP (threads 0..63) + eigen-count binary search (threads 0,1) ----
    float pacc = 0.f;
    if (n < DPE*MM) {
        int d = n >> 2, m = n & 3;
        float lam = Lambda[b*DPE + d];
        pacc = pb2[m];
        #pragma unroll
        for (int h = 0; h < HPSI; h++) {
            float v = fmaf(lam, pW1[m*HPSI + h], pb1[m*HPSI + h]);
            pacc = fmaf(fmaxf(v, 0.f), pW2[m*HPSI + h], pacc);
        }
    }
    if (n < 2) {
        int key = b + n;
        int lo = 0, hi = NSUM;
        while (lo < hi) {
            int mid = (lo + hi) >> 1;
            if (batch[mid] < key) lo = mid + 1; else hi = mid;
        }
        bnds[n] = lo;
    }

    // ---- Projection weights, packed, in registers ----
    u64 wp2[MM][HP/2];
    u64 bps2[HP/2];
    #pragma unroll
    for (int m = 0; m < MM; m++)
        #pragma unroll
        for (int hp = 0; hp < HP/2; hp++)
            wp2[m][hp] = pk2(Wp1[m*HP + 2*hp], Wp1[m*HP + 2*hp + 1]);
    #pragma unroll
    for (int hp = 0; hp < HP/2; hp++) bps2[hp] = pk2(bp1[2*hp], bp1[2*hp+1]);

    __syncthreads();   // V, cnt=0, bnds visible

    // ---- masked Z ----
    if (n < DPE*MM) {
        int c = bnds[1] - bnds[0];
        zs[n] = ((n >> 2) < c) ? pacc : 0.f;
    }
    __syncthreads();   // zs visible

    // ---- Per-thread packed scaled row ----
    u64 An2[MM][DPE/2];
    {
        const float4* vrow = (const float4*)&Vs[n*VPAD];
        #pragma unroll
        for (int q = 0; q < 4; q++) {
            float4 vv = vrow[q];
            #pragma unroll
            for (int m = 0; m < MM; m++) {
                An2[m][2*q]   = pk2(vv.x * zs[(4*q)*MM + m],   vv.y * zs[(4*q+1)*MM + m]);
                An2[m][2*q+1] = pk2(vv.z * zs[(4*q+2)*MM + m], vv.w * zs[(4*q+3)*MM + m]);
            }
        }
    }

    u64 acc2[HP/2];
    #pragma unroll
    for (int h = 0; h < HP/2; h++) acc2[h] = 0ull;

    u64 rp[8];

    // o = 0: diagonal pair (n,n) counted once
    {
        COMPUTE_R2(n);
        #pragma unroll
        for (int h = 0; h < 8; h++) acc2[h] = add2(acc2[h], rp[h]);
    }

    float* xchLo = xch;
    float* xchHi = xch + 4*NN*VPAD;

    // MAIN LOOP: 31 branch-free compute groups; CSR piggybacked pre-barrier.
    for (int g = 0; g < 31; g++) {
        float* bufs = (g & 1) ? xchHi : xchLo;

        #pragma unroll
        for (int j = 0; j < 4; j++) {
            int o = 4*g + 1 + j;
            int k = n + o;                      // replicated V rows, no wrap
            COMPUTE_R2(k);
            u64* xw = (u64*)&bufs[j*NN*VPAD + n*VPAD];
            #pragma unroll
            for (int h = 0; h < 8; h++) {
                acc2[h] = add2(acc2[h], rp[h]);
                xw[h] = rp[h];
            }
        }

        // ---- CSR piggyback (ordering provided by the group barrier) ----
        if (g < 8) {                       // histogram: 512 edges per group
            int e0 = g*512 + n;
            atomicAdd(&cnt[dstp[e0] - base], 1);
            atomicAdd(&cnt[dstp[e0 + 256] - base], 1);
        } else if (g == 8) {               // scan part 1: warp sums
            int v = cnt[n];
            int incl = warp_incl_scan(v, lane);
            if (lane == 31) wsum[n >> 5] = incl;
        } else if (g == 9) {               // scan part 2: offsets (recompute)
            int v = cnt[n];
            int incl = warp_incl_scan(v, lane);
            int pre = 0;
            #pragma unroll
            for (int i = 0; i < 8; i++) pre += (i < (n >> 5)) ? wsum[i] : 0;
            int excl = incl - v + pre;
            start_s[n] = excl;
            cur[n] = excl;
            if (n == 0) start_s[NN] = EPG;
        } else if (g < 18) {               // scatter: 512 edges per group
            int e0 = (g - 10)*512 + n;
            int d0 = dstp[e0] - base;
            int p0 = atomicAdd(&cur[d0], 1);
            srt_s[p0] = srcp[e0] - base;
            int e1 = e0 + 256;
            int d1 = dstp[e1] - base;
            int p1 = atomicAdd(&cur[d1], 1);
            srt_s[p1] = srcp[e1] - base;
        }

        __syncthreads();
        #pragma unroll
        for (int j = 0; j < 4; j++) {
            int o = 4*g + 1 + j;
            int p = (n - o) & 255;
            const ulonglong2* xr = (const ulonglong2*)&bufs[j*NN*VPAD + p*VPAD];
            ulonglong2 a0 = xr[0], a1 = xr[1], a2 = xr[2], a3 = xr[3];
            acc2[0] = add2(acc2[0], a0.x); acc2[1] = add2(acc2[1], a0.y);
            acc2[2] = add2(acc2[2], a1.x); acc2[3] = add2(acc2[3], a1.y);
            acc2[4] = add2(acc2[4], a2.x); acc2[5] = add2(acc2[5], a2.y);
            acc2[6] = add2(acc2[6], a3.x); acc2[7] = add2(acc2[7], a3.y);
        }
    }

    // PEELED FINAL GROUP: offsets 125, 126, 127 (unconditional) + 128 (half).
    {
        float* bufs = xchHi;     // g = 31 is odd
        #pragma unroll
        for (int j = 0; j < 3; j++) {
            int o = 125 + j;
            int k = n + o;
            COMPUTE_R2(k);
            u64* xw = (u64*)&bufs[j*NN*VPAD + n*VPAD];
            #pragma unroll
            for (int h = 0; h < 8; h++) {
                acc2[h] = add2(acc2[h], rp[h]);
                xw[h] = rp[h];
            }
        }
        if (n < 128) {
            int k = n + 128;
            COMPUTE_R2(k);
            u64* xw = (u64*)&bufs[3*NN*VPAD + n*VPAD];
            #pragma unroll
            for (int h = 0; h < 8; h++) {
                acc2[h] = add2(acc2[h], rp[h]);
                xw[h] = rp[h];
            }
        }
        __syncthreads();
        #pragma unroll
        for (int j = 0; j < 3; j++) {
            int o = 125 + j;
            int p = (n - o) & 255;
            const ulonglong2* xr = (const ulonglong2*)&bufs[j*NN*VPAD + p*VPAD];
            ulonglong2 a0 = xr[0], a1 = xr[1], a2 = xr[2], a3 = xr[3];
            acc2[0] = add2(acc2[0], a0.x); acc2[1] = add2(acc2[1], a0.y);
            acc2[2] = add2(acc2[2], a1.x); acc2[3] = add2(acc2[3], a1.y);
            acc2[4] = add2(acc2[4], a2.x); acc2[5] = add2(acc2[5], a2.y);
            acc2[6] = add2(acc2[6], a3.x); acc2[7] = add2(acc2[7], a3.y);
        }
        if (n >= 128) {
            int p = (n - 128) & 255;
            const ulonglong2* xr = (const ulonglong2*)&bufs[3*NN*VPAD + p*VPAD];
            ulonglong2 a0 = xr[0], a1 = xr[1], a2 = xr[2], a3 = xr[3];
            acc2[0] = add2(acc2[0], a0.x); acc2[1] = add2(acc2[1], a0.y);
            acc2[2] = add2(acc2[2], a1.x); acc2[3] = add2(acc2[3], a1.y);
            acc2[4] = add2(acc2[4], a2.x); acc2[5] = add2(acc2[5], a2.y);
            acc2[6] = add2(acc2[6], a3.x); acc2[7] = add2(acc2[7], a3.y);
        }
    }
    __syncthreads();   // all exchange reads complete; xch reusable

    // ---- Epilogue: write x tile, stage GIN weights (alias into xch) ----
    {
        ulonglong2* xw = (ulonglong2*)&xT[n*VPAD];
        xw[0] = make_ulonglong2(acc2[0], acc2[1]);
        xw[1] = make_ulonglong2(acc2[2], acc2[3]);
        xw[2] = make_ulonglong2(acc2[4], acc2[5]);
        xw[3] = make_ulonglong2(acc2[6], acc2[7]);
    }
    #pragma unroll
    for (int i = n; i < HP*HG; i += 256)  Wg1s[i] = Wg1[i];
    #pragma unroll
    for (int i = n; i < HG*DPE; i += 256) Wg2s[i] = Wg2[i];
    if (n < HG)  bg1s[n] = bg1[n];
    if (n >= 256 - DPE) bg2s[n - (256 - DPE)] = bg2[n - (256 - DPE)];
    float ge = 1.f + eps[0];
    __syncthreads();

    // ---- GIN gather (in-smem CSR, built during the o-loop) ----
    u64 agg[8];
    #pragma unroll
    for (int j = 0; j < 8; j++) agg[j] = 0ull;
    {
        int s0 = start_s[n], s1 = start_s[n + 1];
        int idx = s0;
        for (; idx + 2 <= s1; idx += 2) {
            int ea = srt_s[idx], eb = srt_s[idx + 1];
            const ulonglong2* ra = (const ulonglong2*)&xT[ea*VPAD];
            const ulonglong2* rb = (const ulonglong2*)&xT[eb*VPAD];
            ulonglong2 a0=ra[0], a1=ra[1], a2=ra[2], a3=ra[3];
            ulonglong2 b0=rb[0], b1=rb[1], b2=rb[2], b3=rb[3];
            agg[0]=add2(agg[0],a0.x); agg[1]=add2(agg[1],a0.y);
            agg[2]=add2(agg[2],a1.x); agg[3]=add2(agg[3],a1.y);
            agg[4]=add2(agg[4],a2.x); agg[5]=add2(agg[5],a2.y);
            agg[6]=add2(agg[6],a3.x); agg[7]=add2(agg[7],a3.y);
            agg[0]=add2(agg[0],b0.x); agg[1]=add2(agg[1],b0.y);
            agg[2]=add2(agg[2],b1.x); agg[3]=add2(agg[3],b1.y);
            agg[4]=add2(agg[4],b2.x); agg[5]=add2(agg[5],b2.y);
            agg[6]=add2(agg[6],b3.x); agg[7]=add2(agg[7],b3.y);
        }
        if (idx < s1) {
            int e = srt_s[idx];
            const ulonglong2* r = (const ulonglong2*)&xT[e*VPAD];
            ulonglong2 q0=r[0], q1=r[1], q2=r[2], q3=r[3];
            agg[0]=add2(agg[0],q0.x); agg[1]=add2(agg[1],q0.y);
            agg[2]=add2(agg[2],q1.x); agg[3]=add2(agg[3],q1.y);
            agg[4]=add2(agg[4],q2.x); agg[5]=add2(agg[5],q2.y);
            agg[6]=add2(agg[6],q3.x); agg[7]=add2(agg[7],q3.y);
        }
    }

    // y = (1+eps)*x_self + agg  (x_self = acc2 still in registers)
    u64 ge2 = pk2(ge, ge);
    u64 yfull[8];
    #pragma unroll
    for (int j = 0; j < 8; j++) yfull[j] = fma2(ge2, acc2[j], agg[j]);

    // Layer 1: tg[64] = y @ Wg1 + bg1 (full, per thread)
    u64 tg[HG/2];
    {
        const u64* bu = (const u64*)bg1s;
        #pragma unroll
        for (int j = 0; j < HG/2; j++) tg[j] = bu[j];
    }
    #pragma unroll
    for (int hq = 0; hq < 8; hq++) {
        float ylo, yhi; upk2(yfull[hq], ylo, yhi);
        u64 ya = pk2(ylo, ylo), yb = pk2(yhi, yhi);
        const u64* wa = (const u64*)&Wg1s[(2*hq)*HG];
        const u64* wb = (const u64*)&Wg1s[(2*hq+1)*HG];
        #pragma unroll
        for (int j = 0; j < HG/2; j++) {
            tg[j] = fma2(ya, wa[j], tg[j]);
            tg[j] = fma2(yb, wb[j], tg[j]);
        }
    }

    // ReLU + layer 2: out[16] = relu(tg) @ Wg2 + bg2
    u64 o2[DPE/2];
    {
        const u64* bu = (const u64*)bg2s;
        #pragma unroll
        for (int d = 0; d < DPE/2; d++) o2[d] = bu[d];
    }
    #pragma unroll
    for (int j = 0; j < HG/2; j++) {
        float t0, t1; upk2(tg[j], t0, t1);
        t0 = fmaxf(t0, 0.f); t1 = fmaxf(t1, 0.f);
        u64 ta = pk2(t0, t0), tb = pk2(t1, t1);
        const u64* wa = (const u64*)&Wg2s[(2*j)*DPE];
        const u64* wb = (const u64*)&Wg2s[(2*j+1)*DPE];
        #pragma unroll
        for (int d = 0; d < DPE/2; d++) {
            o2[d] = fma2(ta, wa[d], o2[d]);
            o2[d] = fma2(tb, wb[d], o2[d]);
        }
    }

    ulonglong2* op = (ulonglong2*)(out + (size_t)(b*NN + n)*DPE);
    op[0] = make_ulonglong2(o2[0], o2[1]);
    op[1] = make_ulonglong2(o2[2], o2[3]);
    op[2] = make_ulonglong2(o2[4], o2[5]);
    op[3] = make_ulonglong2(o2[6], o2[7]);
}

// ---------------------------------------------------------------------------
extern "C" void kernel_launch(void* const* d_in, const int* in_sizes, int n_in,
                              void* d_out, int out_size)
{
    const float* Lambda = (const float*)d_in[0];
    const float* V      = (const float*)d_in[1];
    const float* pW1    = (const float*)d_in[2];
    const float* pb1    = (const float*)d_in[3];
    const float* pW2    = (const float*)d_in[4];
    const float* pb2    = (const float*)d_in[5];
    const float* Wp1    = (const float*)d_in[6];
    const float* bp1    = (const float*)d_in[7];
    const float* Wg1    = (const float*)d_in[8];
    const float* bg1    = (const float*)d_in[9];
    const float* Wg2    = (const float*)d_in[10];
    const float* bg2    = (const float*)d_in[11];
    const float* eps    = (const float*)d_in[12];
    const int*   edge_index = (const int*)d_in[13];
    const int*   batch  = (const int*)d_in[14];
    float* out = (float*)d_out;

    // Vs(2*5120) + xch(8*5120) + zs(64) + srt(4096) + start(260) + cnt/cur(512)
    const int smemF = (10*NN*VPAD + 64 + 4096 + 260 + 512) * (int)sizeof(float); // 224528 B
    cudaFuncSetAttribute(kernelF, cudaFuncAttributeMaxDynamicSharedMemorySize, smemF);

    kernelF<<<NB, 256, smemF>>>(V, Lambda, pW1, pb1, pW2, pb2, Wp1, bp1,
                                Wg1, bg1, Wg2, bg2, eps, batch, edge_index, out);
}